// round 16
// baseline (speedup 1.0000x reference)
#include <cuda_runtime.h>
#include <cstdint>

// Segment max-pool — partials + combine (no atomics, no init/decode):
//   point_features: (B, C, N) float32   [d_in[0]]
//   box_ids_of_pts: (B, N)    int32/int64 (auto-detected inline)  [d_in[2]]
//   out:            (B*S, C)  float32   S = 100
//
// Grid = (chunks=N/4096, B, SLABS=8). Per block: counting-sort its chunk's
// labels once; per 2-channel group: cp.async-prefetch group g+1 while
// reducing group g (fmaxf over LDS gathers). Each (seg, half, ch) task
// writes a plain-float partial (-inf if empty); combine kernel maxes the
// 2*numChunks partials per output cell.

#define S_SEG    100
#define CHUNK    4096
#define NTHREADS 256
#define CG       2
#define SLABS    8
#define TILE_PAD 8
#define ROWF     (CHUNK + TILE_PAD)
#define TILE_BYTES (2 * CG * ROWF * 4)          // 65,664
#define IDX_BYTES  (CHUNK * 2)                  // 8,192
#define SMEM_BYTES (TILE_BYTES + IDX_BYTES + (3 * S_SEG + 1) * 4 + 12)

#define MAX_PARTS 64
#define MAX_CELLS 204800
__device__ float g_part[MAX_PARTS * MAX_CELLS];  // 52 MB scratch (static, legal)

__device__ __forceinline__ void cp_async16(void* smem_dst, const void* gmem_src) {
    unsigned sa = (unsigned)__cvta_generic_to_shared(smem_dst);
    asm volatile("cp.async.cg.shared.global [%0], [%1], 16;\n"
                 :: "r"(sa), "l"(gmem_src) : "memory");
}

__global__ __launch_bounds__(NTHREADS)
void seg_max_kernel(const float* __restrict__ pf,
                    const int* __restrict__ lab32,
                    int C, int N, int cells) {
    extern __shared__ __align__(16) char dyn[];
    float* s_tile = (float*)dyn;                         // [2][CG][ROWF]
    unsigned short* s_lab = (unsigned short*)dyn;        // alias: sort phase only
    unsigned short* s_idx = (unsigned short*)(dyn + TILE_BYTES);
    int* s_cnt = (int*)(dyn + TILE_BYTES + IDX_BYTES);   // [100]
    int* s_off = s_cnt + S_SEG;                          // [101]
    int* s_cur = s_off + S_SEG + 1;                      // [100]

    const int tid = threadIdx.x;
    const int b = blockIdx.y;
    const int chPerSlab = C / SLABS;                     // 16
    const int chBase = blockIdx.z * chPerSlab;
    const int n0 = blockIdx.x * CHUNK;
    const int len = min(CHUNK, N - n0);
    const size_t base = (size_t)b * N + n0;

    // ---- inline dtype detection on the global first 128 word-pairs:
    // int64 labels in [0,100) look like [lab,0,lab,0,...] as int32 words.
    int okPair = 1;
    if (tid < 128) {
        int lo = lab32[2 * tid], hi = lab32[2 * tid + 1];
        okPair = (hi == 0 && lo >= 0 && lo < S_SEG) ? 1 : 0;
    }
    const int is64 = __syncthreads_and(okPair);

    for (int s = tid; s < S_SEG; s += NTHREADS) s_cnt[s] = 0;
    __syncthreads();

    // ---- labels + histogram ----
    for (int i = tid; i < len; i += NTHREADS) {
        long long l;
        if (is64) {
            int2 w = ((const int2*)lab32)[base + i];
            l = ((long long)w.y << 32) | (unsigned int)w.x;
        } else {
            l = lab32[base + i];
        }
        if (l >= 0 && l < S_SEG) {
            s_lab[i] = (unsigned short)l;
            atomicAdd(&s_cnt[(int)l], 1);
        } else {
            s_lab[i] = 0xFFFF;
        }
    }
    __syncthreads();

    if (tid == 0) {
        int run = 0;
        #pragma unroll 4
        for (int s = 0; s < S_SEG; s++) { s_off[s] = run; run += s_cnt[s]; }
        s_off[S_SEG] = run;
    }
    __syncthreads();
    for (int s = tid; s < S_SEG; s += NTHREADS) s_cur[s] = s_off[s];
    __syncthreads();

    for (int i = tid; i < len; i += NTHREADS) {
        unsigned short l = s_lab[i];
        if (l != 0xFFFF) {
            int pos = atomicAdd(&s_cur[l], 1);
            s_idx[pos] = (unsigned short)i;
        }
    }
    __syncthreads();   // s_lab dead after this point (tile may overwrite)

    // ---- double-buffered channel groups within this slab ----
    const int nGroups = chPerSlab / CG;                  // 8
    const int lenAligned = len & ~3;
    const int nVec = (CHUNK / 4) * CG;

    auto tileRow = [&](int buf, int cl) -> float* {
        return s_tile + (buf * CG + cl) * ROWF;
    };

    auto stage = [&](int g, int buf) {
        const int ch0 = chBase + g * CG;
        #pragma unroll 2
        for (int k = tid; k < nVec; k += NTHREADS) {
            const int e = k * 4;
            const int cl = e / CHUNK;
            const int i = e & (CHUNK - 1);
            if (i < lenAligned) {
                const float* src = pf + (((size_t)b * C + ch0 + cl) * N + n0 + i);
                cp_async16(tileRow(buf, cl) + i, src);
            }
        }
        asm volatile("cp.async.commit_group;\n" ::: "memory");
    };

    stage(0, 0);

    const size_t partStride = (size_t)cells;
    const int partChunk = blockIdx.x * 2;

    for (int g = 0; g < nGroups; g++) {
        const int buf = g & 1;
        if (g + 1 < nGroups) {
            stage(g + 1, buf ^ 1);
            asm volatile("cp.async.wait_group 1;\n" ::: "memory");
        } else {
            asm volatile("cp.async.wait_group 0;\n" ::: "memory");
        }
        __syncthreads();

        // scalar tail (len % 4 != 0) — never taken for N = 65536
        if (lenAligned < len) {
            const int ch0 = chBase + g * CG;
            #pragma unroll
            for (int cl = 0; cl < CG; cl++) {
                const float* src = pf + (((size_t)b * C + ch0 + cl) * N + n0);
                for (int i = lenAligned + tid; i < len; i += NTHREADS)
                    tileRow(buf, cl)[i] = src[i];
            }
            __syncthreads();
        }

        // reduce: task = (seg, half, channel-in-group); 400 tasks.
        // Unconditional plain-float partial store (-inf if empty).
        const int ch0 = chBase + g * CG;
        for (int task = tid; task < S_SEG * 2 * CG; task += NTHREADS) {
            const int seg = task >> 2;
            const int sub = task & 3;
            const int cl = sub & 1;
            const int half = sub >> 1;
            const int q0 = s_off[seg];
            const int q1 = s_off[seg + 1];
            const int mid = (q0 + q1 + 1) >> 1;
            const int p0 = half ? mid : q0;
            const int p1 = half ? q1 : mid;
            float m = __int_as_float(0xFF800000);        // -inf
            const float* row = tileRow(buf, cl);
            #pragma unroll 4
            for (int p = p0; p < p1; p++)
                m = fmaxf(m, row[s_idx[p]]);
            g_part[(size_t)(partChunk + half) * partStride
                   + ((size_t)(b * S_SEG + seg)) * C + ch0 + cl] = m;
        }
        __syncthreads();   // buffer reused two iterations later
    }
}

__global__ void combine_kernel(float* __restrict__ out, int cells, int nParts) {
    int i = blockIdx.x * blockDim.x + threadIdx.x;
    if (i >= cells) return;
    float m = __int_as_float(0xFF800000);                // -inf
    for (int k = 0; k < nParts; k++)
        m = fmaxf(m, g_part[(size_t)k * cells + i]);
    out[i] = m;
}

extern "C" void kernel_launch(void* const* d_in, const int* in_sizes, int n_in,
                              void* d_out, int out_size) {
    const float* pf = (const float*)d_in[0];
    const int* lab32 = (const int*)d_in[2];

    const int pf_elems = in_sizes[0];      // B*C*N
    const int lab_elems = in_sizes[2];     // B*N
    const int C = pf_elems / lab_elems;    // 128
    const int B = out_size / (S_SEG * C);  // 8
    const int N = lab_elems / B;           // 65536

    float* outF = (float*)d_out;

    cudaFuncSetAttribute(seg_max_kernel,
                         cudaFuncAttributeMaxDynamicSharedMemorySize, SMEM_BYTES);

    const int numChunks = (N + CHUNK - 1) / CHUNK;       // 16
    dim3 grid(numChunks, B, SLABS);
    seg_max_kernel<<<grid, NTHREADS, SMEM_BYTES>>>(pf, lab32, C, N, out_size);

    combine_kernel<<<(out_size + 255) / 256, 256>>>(outF, out_size, numChunks * 2);
}